// round 14
// baseline (speedup 1.0000x reference)
#include <cuda_runtime.h>

#define B_LEN 32
#define T_IN  128
#define T_LEN 129
#define M_LEN 40
#define NPIX  (B_LEN*T_LEN*M_LEN)            // 165,120
#define NTOT  (NPIX*64)
typedef unsigned long long ull;

// acts: [(b*40+m)*2+half][t][lane]
__device__ float  g_acts[NTOT];
// per-half spike lists: pixel block of 64B; half h entries in bytes [h*32, h*32+n),
// each a lane id 0..31, padded to a multiple of 4 with sentinel (h0:64, h1:32).
// counts: g_cntX[pix*2+half] (1 byte each).
__device__ unsigned char g_cil1[NPIX * 64];
__device__ unsigned char g_cnt1[NPIX * 2];
__device__ unsigned char g_cil2[NPIX * 64];
__device__ unsigned char g_cnt2[NPIX * 2];
__device__ unsigned g_nz[1280];              // layer-3 per-chain maybe-nonzero flag
__device__ ull g_rm[B_LEN * T_LEN];          // layer-2 row mask: bit m set if any spike
// conv weight tables: float idx = (tap*65 + ci)*64 + lane*2 + half
//   (co = half*32+lane); 256B per (tap,ci) block; row ci=64 all zeros (sentinel).
__device__ float4 g_wq2[49920 / 4];
__device__ float4 g_wq3[49920 / 4];
__device__ float4 g_wft[30720 / 4];          // [o][m][c]
__device__ float  g_cnt[B_LEN * M_LEN * 64]; // [b][m][c]

__device__ __forceinline__ float lif_tau_div(float num) {
    const float TAUF = 10.0f / 7.0f;
    return __fdiv_rn(num, TAUF);
}
__device__ __forceinline__ void add_f32x2(ull& acc, ull w) {
    asm("add.rn.f32x2 %0, %1, %2;" : "=l"(acc) : "l"(acc), "l"(w));
}

// ---------------- weight transposes + flag/mask reset ----------------
__global__ void k_transpose(const float* __restrict__ w2, const float* __restrict__ w3,
                            const float* __restrict__ wf) {
    int i = blockIdx.x * 256 + threadIdx.x;
    if (i < 1280) g_nz[i] = 0;
    if (i < B_LEN * T_LEN) g_rm[i] = 0ull;
    if (i < 2 * 49920) {
        int which = i >= 49920;
        int j   = i - which * 49920;
        int blk = j >> 6;           // tap*65 + ci
        int r   = j & 63;
        int lane = r >> 1;
        int half = r & 1;
        int tap = blk / 65;
        int ci  = blk % 65;
        float v = 0.0f;
        const float* w = which ? w3 : w2;
        if (ci < 64) v = w[(half * 32 + lane) * 768 + ci * 12 + tap];
        (which ? (float*)g_wq3 : (float*)g_wq2)[j] = v;
    } else if (i < 2 * 49920 + 30720) {
        int j = i - 2 * 49920;
        int c = j & 63;
        int m = (j >> 6) % 40;
        int o = j / 2560;
        ((float*)g_wft)[j] = wf[o * 2560 + c * 40 + m];
    }
}

// ---------------- per-half spike emit with sentinel padding ----------------
__device__ __forceinline__ unsigned emit_half(bool sp, int lane, unsigned lml,
                                              int pix, int half,
                                              unsigned char* __restrict__ cil,
                                              unsigned char* __restrict__ cnt) {
    unsigned bal = __ballot_sync(0xffffffffu, sp);
    int n = __popc(bal);
    size_t base = (size_t)pix * 64 + half * 32;
    if (sp) cil[base + __popc(bal & lml)] = (unsigned char)lane;
    int pad = (4 - (n & 3)) & 3;
    if (lane < pad) cil[base + n + lane] = (unsigned char)(half ? 32 : 64);
    if (lane == 0) cnt[pix * 2 + half] = (unsigned char)n;
    return bal;
}

// ---------------- conv1 + LIF1 fused: warp per (b,m,half) chain -------------
__global__ void __launch_bounds__(256) k_conv1_lif(const float* __restrict__ x,
                                                   const float* __restrict__ w1) {
    int w    = (blockIdx.x * 256 + threadIdx.x) >> 5;   // 2560 chains
    int lane = threadIdx.x & 31;
    unsigned lml = (1u << lane) - 1u;
    int b    = w / 80;
    int r    = w % 80;
    int m    = r >> 1;
    int half = r & 1;
    int co   = half * 32 + lane;

    float wr[12];
#pragma unroll
    for (int k = 0; k < 12; ++k) wr[k] = w1[co * 12 + k];

    const float* xb = x + (size_t)b * T_IN * M_LEN + m;
    bool c0 = (m - 1 >= 0);
    bool c2 = (m + 1 < M_LEN);

    float win[4][3];
#pragma unroll
    for (int i = 0; i < 4; ++i)
#pragma unroll
        for (int j = 0; j < 3; ++j) win[i][j] = 0.0f;
#pragma unroll
    for (int i = 2; i < 4; ++i) {
        int ti = i - 2;
        win[i][0] = c0 ? xb[ti * M_LEN - 1] : 0.0f;
        win[i][1] = xb[ti * M_LEN];
        win[i][2] = c2 ? xb[ti * M_LEN + 1] : 0.0f;
    }

    float v = 0.0f;
    for (int t = 0; t < T_LEN; ++t) {
        float acc = 0.0f;
#pragma unroll
        for (int kh = 0; kh < 4; ++kh)
#pragma unroll
            for (int kw = 0; kw < 3; ++kw)
                acc = fmaf(wr[kh * 3 + kw], win[kh][kw], acc);

        v = v + lif_tau_div(acc - v);
        bool sp = (v >= 1.0f);
        if (sp) v = 0.0f;
        emit_half(sp, lane, lml, (b * T_LEN + t) * M_LEN + m, half, g_cil1, g_cnt1);

#pragma unroll
        for (int i = 0; i < 3; ++i)
#pragma unroll
            for (int j = 0; j < 3; ++j) win[i][j] = win[i + 1][j];
        int ti = t + 2;
        bool rv = (ti < T_IN);
        win[3][0] = (rv && c0) ? xb[ti * M_LEN - 1] : 0.0f;
        win[3][1] = rv ? xb[ti * M_LEN] : 0.0f;
        win[3][2] = (rv && c2) ? xb[ti * M_LEN + 1] : 0.0f;
    }
}

// ---------------- staging: 12 counts + 24 list words (full MLP) -------------
template<int PADT, int DILT, int PADM, int DILM>
__device__ __forceinline__ void load_pix(int pix,
                                         const unsigned char* __restrict__ cil,
                                         const unsigned char* __restrict__ cntb,
                                         unsigned short (&cc)[12], unsigned (&qa)[12],
                                         unsigned (&qb)[12]) {
    int b = pix / (T_LEN * M_LEN);
    int r = pix % (T_LEN * M_LEN);
    int t = r / M_LEN;
    int m = r % M_LEN;
    int rowb = b * T_LEN * M_LEN;
#pragma unroll
    for (int kh = 0; kh < 4; ++kh)
#pragma unroll
        for (int kw = 0; kw < 3; ++kw) {
            int tap = kh * 3 + kw;
            int ti = t - PADT + DILT * kh;
            int mi = m - PADM + DILM * kw;
            bool v = ((unsigned)ti < (unsigned)T_LEN) & ((unsigned)mi < (unsigned)M_LEN);
            int ip = v ? (rowb + ti * M_LEN + mi) : 0;
            cc[tap] = v ? *(const unsigned short*)(cntb + ip * 2) : (unsigned short)0;
            const unsigned* lp = (const unsigned*)(cil + (size_t)ip * 64);
            qa[tap] = lp[0];   // half0 entries 0..3
            qb[tap] = lp[8];   // half1 entries 0..3
        }
}

// decode one group of 4 sentinel-padded entries against a weight base
__device__ __forceinline__ void dec4(ull& acc, const char* wb, unsigned q) {
#pragma unroll
    for (int e = 0; e < 4; ++e) {
        int ci = __byte_perm(q, 0, 0x4440 + e);
        add_f32x2(acc, *(const ull*)(wb + ci * 256));
    }
}

// ---------------- sconv2: warp/output, software-pipelined, per-half decode --
template<int PADT, int DILT, int PADM, int DILM>
__global__ void __launch_bounds__(512, 1) k_sgather(const unsigned char* __restrict__ cil,
                                                    const unsigned char* __restrict__ cntb,
                                                    const float4* __restrict__ wtg,
                                                    float* __restrict__ acts) {
    extern __shared__ char wsm[];   // 199680 B: [tap][ci(65)] 256B blocks
    {
        float4* d = (float4*)wsm;
        for (int i = threadIdx.x; i < 12480; i += 512) d[i] = wtg[i];
    }
    __syncthreads();

    int lane = threadIdx.x & 31;
    const char* wlane = wsm + lane * 8;
    int wid  = (blockIdx.x * 512 + threadIdx.x) >> 5;
    int nw   = gridDim.x * 16;

    unsigned short cc[12];
    unsigned qa[12], qb[12];
    if (wid < NPIX)
        load_pix<PADT, DILT, PADM, DILM>(wid, cil, cntb, cc, qa, qb);

    for (int pix = wid; pix < NPIX; pix += nw) {
        unsigned short ccn[12];
        unsigned qan[12], qbn[12];
        int pn = pix + nw;
        if (pn < NPIX)
            load_pix<PADT, DILT, PADM, DILM>(pn, cil, cntb, ccn, qan, qbn);

        int b = pix / (T_LEN * M_LEN);
        int r = pix % (T_LEN * M_LEN);
        int t = r / M_LEN;
        int m = r % M_LEN;
        int rowb = b * T_LEN * M_LEN;

        ull acc = 0ull;
#pragma unroll
        for (int kh = 0; kh < 4; ++kh)
#pragma unroll
            for (int kw = 0; kw < 3; ++kw) {
                int tap = kh * 3 + kw;
                int cp = (int)cc[tap];
                if (!cp) continue;
                int n0 = cp & 255;
                int n1 = cp >> 8;
                const char* wtap = wlane + tap * (65 * 256);
                if (n0) {
                    dec4(acc, wtap, qa[tap]);
                    if (n0 > 4) {
                        int ti = t - PADT + DILT * kh;
                        int mi = m - PADM + DILM * kw;
                        const unsigned* lp = (const unsigned*)
                            (cil + (size_t)(rowb + ti * M_LEN + mi) * 64);
                        for (int j = 4; j < n0; j += 4) dec4(acc, wtap, lp[j >> 2]);
                    }
                }
                if (n1) {
                    const char* wtap1 = wtap + 32 * 256;   // sentinel 32 -> row 64 (zeros)
                    dec4(acc, wtap1, qb[tap]);
                    if (n1 > 4) {
                        int ti = t - PADT + DILT * kh;
                        int mi = m - PADM + DILM * kw;
                        const unsigned* lp = (const unsigned*)
                            (cil + (size_t)(rowb + ti * M_LEN + mi) * 64);
                        for (int j = 4; j < n1; j += 4) dec4(acc, wtap1, lp[8 + (j >> 2)]);
                    }
                }
            }

        union { ull u; float2 f; } cv;
        cv.u = acc;
        size_t row = ((size_t)(b * M_LEN + m) * 2) * T_LEN + t;
        acts[row * 32 + lane]           = cv.f.x;
        acts[(row + T_LEN) * 32 + lane] = cv.f.y;

#pragma unroll
        for (int i = 0; i < 12; ++i) {
            cc[i] = ccn[i];
            qa[i] = qan[i];
            qb[i] = qbn[i];
        }
    }
}

// ---------------- sconv3: row-mask early-out (layer-2 nearly empty) ---------
template<int PADT, int DILT, int PADM, int DILM>
__global__ void __launch_bounds__(512, 1) k_sgather_m(const unsigned char* __restrict__ cil,
                                                      const unsigned char* __restrict__ cntb,
                                                      const float4* __restrict__ wtg,
                                                      float* __restrict__ acts) {
    extern __shared__ char wsm[];
    {
        float4* d = (float4*)wsm;
        for (int i = threadIdx.x; i < 12480; i += 512) d[i] = wtg[i];
    }
    __syncthreads();

    int lane = threadIdx.x & 31;
    const char* wlane = wsm + lane * 8;
    int wid  = (blockIdx.x * 512 + threadIdx.x) >> 5;
    int nw   = gridDim.x * 16;

    for (int pix = wid; pix < NPIX; pix += nw) {
        int b = pix / (T_LEN * M_LEN);
        int r = pix % (T_LEN * M_LEN);
        int t = r / M_LEN;
        int m = r % M_LEN;
        int rowb = b * T_LEN * M_LEN;

        // m-bits for the 3 kw offsets (warp-constant per pixel)
        ull mb = 0;
#pragma unroll
        for (int kw = 0; kw < 3; ++kw) {
            int mi = m - PADM + DILM * kw;
            if ((unsigned)mi < (unsigned)M_LEN) mb |= 1ull << mi;
        }
        // 4 row-mask loads
        ull need = 0;
#pragma unroll
        for (int kh = 0; kh < 4; ++kh) {
            int ti = t - PADT + DILT * kh;
            if ((unsigned)ti < (unsigned)T_LEN) need |= g_rm[b * T_LEN + ti];
        }
        need &= mb;

        ull acc = 0ull;
        if (need) {
            if (lane == 0) g_nz[b * M_LEN + m] = 1u;   // superset flag
            unsigned short cc[12];
            unsigned qa[12], qb[12];
            load_pix<PADT, DILT, PADM, DILM>(pix, cil, cntb, cc, qa, qb);
#pragma unroll
            for (int kh = 0; kh < 4; ++kh)
#pragma unroll
                for (int kw = 0; kw < 3; ++kw) {
                    int tap = kh * 3 + kw;
                    int cp = (int)cc[tap];
                    if (!cp) continue;
                    int n0 = cp & 255;
                    int n1 = cp >> 8;
                    const char* wtap = wlane + tap * (65 * 256);
                    if (n0) {
                        dec4(acc, wtap, qa[tap]);
                        if (n0 > 4) {
                            int ti = t - PADT + DILT * kh;
                            int mi = m - PADM + DILM * kw;
                            const unsigned* lp = (const unsigned*)
                                (cil + (size_t)(rowb + ti * M_LEN + mi) * 64);
                            for (int j = 4; j < n0; j += 4) dec4(acc, wtap, lp[j >> 2]);
                        }
                    }
                    if (n1) {
                        const char* wtap1 = wtap + 32 * 256;
                        dec4(acc, wtap1, qb[tap]);
                        if (n1 > 4) {
                            int ti = t - PADT + DILT * kh;
                            int mi = m - PADM + DILM * kw;
                            const unsigned* lp = (const unsigned*)
                                (cil + (size_t)(rowb + ti * M_LEN + mi) * 64);
                            for (int j = 4; j < n1; j += 4) dec4(acc, wtap1, lp[8 + (j >> 2)]);
                        }
                    }
                }
        }
        union { ull u; float2 f; } cv;
        cv.u = acc;
        size_t row = ((size_t)(b * M_LEN + m) * 2) * T_LEN + t;
        acts[row * 32 + lane]           = cv.f.x;
        acts[(row + T_LEN) * 32 + lane] = cv.f.y;
    }
}

// ---------------- LIF scan: warp per (b,m,half), 16-deep prefetch -----------
// MODE 0: emit lists + row mask. MODE 1: counts with nz skip.
template<int MODE>
__global__ void __launch_bounds__(256) k_lif_scan(const float* __restrict__ acts,
                                                  unsigned char* __restrict__ cil,
                                                  unsigned char* __restrict__ cntb) {
    int w    = (blockIdx.x * 256 + threadIdx.x) >> 5;   // 2560
    int lane = threadIdx.x & 31;
    unsigned lml = (1u << lane) - 1u;
    int b    = w / 80;
    int r    = w % 80;
    int m    = r >> 1;
    int half = r & 1;
    int chain = b * 40 + m;

    if (MODE == 1) {
        if (g_nz[chain] == 0) {   // all-zero acts: v stays exactly 0
            g_cnt[b * 2560 + m * 64 + half * 32 + lane] = 0.0f;
            return;
        }
    }

    const float* p = acts + ((size_t)(chain * 2 + half) * T_LEN) * 32 + lane;

    float v = 0.0f, scnt = 0.0f;
    float buf[16];
#pragma unroll
    for (int i = 0; i < 16; ++i) buf[i] = p[i * 32];

    for (int t16 = 0; t16 < 128; t16 += 16) {
#pragma unroll
        for (int k = 0; k < 16; ++k) {
            int t = t16 + k;
            float a = buf[k];
            int tn = t + 16;
            if (tn < T_LEN) buf[k] = p[tn * 32];
            v = v + lif_tau_div(a - v);
            bool sp = (v >= 1.0f);
            if (sp) v = 0.0f;
            if (MODE == 0) {
                unsigned bal = emit_half(sp, lane, lml, (b * T_LEN + t) * M_LEN + m,
                                         half, cil, cntb);
                if (bal && lane == 0)
                    atomicOr(&g_rm[b * T_LEN + t], 1ull << m);
            } else {
                scnt += sp ? 1.0f : 0.0f;
            }
        }
    }
    {   // t = 128
        float a = buf[0];
        v = v + lif_tau_div(a - v);
        bool sp = (v >= 1.0f);
        if (sp) v = 0.0f;
        if (MODE == 0) {
            unsigned bal = emit_half(sp, lane, lml, (b * T_LEN + 128) * M_LEN + m,
                                     half, cil, cntb);
            if (bal && lane == 0)
                atomicOr(&g_rm[b * T_LEN + 128], 1ull << m);
        } else {
            scnt += sp ? 1.0f : 0.0f;
        }
    }
    if (MODE == 1)
        g_cnt[b * 2560 + m * 64 + half * 32 + lane] = scnt;
}

// ---------------- FC + mean ----------------
__global__ void k_fc(const float* __restrict__ bf, float* __restrict__ out) {
    int o = blockIdx.x;
    int b = blockIdx.y;
    int tid = threadIdx.x;   // 128
    const float* wft = (const float*)g_wft;
    float p = 0.0f;
    for (int i = tid; i < 2560; i += 128)
        p = fmaf(g_cnt[b * 2560 + i], wft[o * 2560 + i], p);
#pragma unroll
    for (int off = 16; off; off >>= 1) p += __shfl_down_sync(0xffffffffu, p, off);
    __shared__ float wsum[4];
    if ((tid & 31) == 0) wsum[tid >> 5] = p;
    __syncthreads();
    if (tid == 0) {
        float tt = wsum[0] + wsum[1] + wsum[2] + wsum[3];
        out[b * 12 + o] = bf[o] + tt / 129.0f;
    }
}

#define SG_SMEM 199680

extern "C" void kernel_launch(void* const* d_in, const int* in_sizes, int n_in,
                              void* d_out, int out_size) {
    const float* x  = (const float*)d_in[0];
    const float* w1 = (const float*)d_in[1];
    const float* w2 = (const float*)d_in[2];
    const float* w3 = (const float*)d_in[3];
    const float* wf = (const float*)d_in[4];
    const float* bf = (const float*)d_in[5];
    float* out = (float*)d_out;

    cudaFuncSetAttribute(k_sgather<6, 4, 3, 3>,
                         cudaFuncAttributeMaxDynamicSharedMemorySize, SG_SMEM);
    cudaFuncSetAttribute(k_sgather_m<24, 16, 9, 9>,
                         cudaFuncAttributeMaxDynamicSharedMemorySize, SG_SMEM);

    unsigned char* c1 = nullptr; cudaGetSymbolAddress((void**)&c1, g_cil1);
    unsigned char* n1 = nullptr; cudaGetSymbolAddress((void**)&n1, g_cnt1);
    unsigned char* c2 = nullptr; cudaGetSymbolAddress((void**)&c2, g_cil2);
    unsigned char* n2 = nullptr; cudaGetSymbolAddress((void**)&n2, g_cnt2);
    float* aA = nullptr; cudaGetSymbolAddress((void**)&aA, g_acts);
    float4* wq2 = nullptr; cudaGetSymbolAddress((void**)&wq2, g_wq2);
    float4* wq3 = nullptr; cudaGetSymbolAddress((void**)&wq3, g_wq3);

    k_transpose<<<510, 256>>>(w2, w3, wf);                        // 1
    k_conv1_lif<<<320, 256>>>(x, w1);                             // 2
    k_sgather<6, 4, 3, 3><<<148, 512, SG_SMEM>>>(c1, n1, wq2, aA); // 3
    k_lif_scan<0><<<320, 256>>>(aA, c2, n2);                      // 4 (profiled)
    k_sgather_m<24, 16, 9, 9><<<148, 512, SG_SMEM>>>(c2, n2, wq3, aA); // 5
    k_lif_scan<1><<<320, 256>>>(aA, nullptr, nullptr);            // 6
    k_fc<<<dim3(12, 32), 128>>>(bf, out);                         // 7
}

// round 15
// speedup vs baseline: 1.3624x; 1.3624x over previous
#include <cuda_runtime.h>

#define B_LEN 32
#define T_IN  128
#define T_LEN 129
#define M_LEN 40
#define NPIX  (B_LEN*T_LEN*M_LEN)            // 165,120
#define NTOT  (NPIX*64)
typedef unsigned long long ull;

// acts: [(b*40+m)*2+half][t][lane]
__device__ float  g_acts[NTOT];
// merged spike lists: per pixel up to 64 byte entries (ci 0..63 ascending),
// padded with sentinel 64 to a multiple of 4. count: 1 byte (unpadded n).
__device__ unsigned char g_cil1[NPIX * 64];
__device__ unsigned char g_cnt1[NPIX];
__device__ unsigned char g_cil2[NPIX * 64];
__device__ unsigned char g_cnt2[NPIX];
__device__ unsigned g_nz[1280];
__device__ ull g_rm[B_LEN * T_LEN];          // layer-2 row mask: bit m if any spike
// conv weight tables: float idx = (tap*65 + ci)*64 + lane*2 + half
//   (co = half*32+lane); 256B per (tap,ci) block -> LDS.64 at lane*8, 2 wavefronts.
//   ci==64 rows are zeros (sentinel). 49920 floats each.
__device__ float4 g_wq2[49920 / 4];
__device__ float4 g_wq3[49920 / 4];
__device__ float4 g_wft[30720 / 4];          // [o][m][c]
__device__ float  g_cnt[B_LEN * M_LEN * 64]; // [b][m][c]

__device__ __forceinline__ float lif_tau_div(float num) {
    const float TAUF = 10.0f / 7.0f;
    return __fdiv_rn(num, TAUF);
}
__device__ __forceinline__ void add_f32x2(ull& acc, ull w) {
    asm("add.rn.f32x2 %0, %1, %2;" : "=l"(acc) : "l"(acc), "l"(w));
}

// ---------------- weight transposes + flag/mask reset ----------------
__global__ void k_transpose(const float* __restrict__ w2, const float* __restrict__ w3,
                            const float* __restrict__ wf) {
    int i = blockIdx.x * 256 + threadIdx.x;
    if (i < 1280) g_nz[i] = 0;
    if (i < B_LEN * T_LEN) g_rm[i] = 0ull;
    if (i < 2 * 49920) {
        int which = i >= 49920;
        int j   = i - which * 49920;
        int blk = j >> 6;           // tap*65 + ci
        int r   = j & 63;
        int lane = r >> 1;
        int half = r & 1;
        int tap = blk / 65;
        int ci  = blk % 65;
        float v = 0.0f;
        const float* w = which ? w3 : w2;
        if (ci < 64) v = w[(half * 32 + lane) * 768 + ci * 12 + tap];
        (which ? (float*)g_wq3 : (float*)g_wq2)[j] = v;
    } else if (i < 2 * 49920 + 30720) {
        int j = i - 2 * 49920;
        int c = j & 63;
        int m = (j >> 6) % 40;
        int o = j / 2560;
        ((float*)g_wft)[j] = wf[o * 2560 + c * 40 + m];
    }
}

__global__ void k_nop() {}

// ---------------- merged spike emit (warp holds both halves) ----------------
// returns total spike count n for this pixel
__device__ __forceinline__ int emit_merged(bool s0, bool s1, int lane, unsigned lml,
                                           int pix, unsigned char* __restrict__ cil,
                                           unsigned char* __restrict__ cnt) {
    unsigned b0 = __ballot_sync(0xffffffffu, s0);
    unsigned b1 = __ballot_sync(0xffffffffu, s1);
    int n0 = __popc(b0);
    int n  = n0 + __popc(b1);
    size_t base = (size_t)pix * 64;
    if (s0) cil[base + __popc(b0 & lml)]      = (unsigned char)lane;
    if (s1) cil[base + n0 + __popc(b1 & lml)] = (unsigned char)(32 + lane);
    int pad = (4 - (n & 3)) & 3;
    if (lane < pad) cil[base + n + lane] = (unsigned char)64;   // sentinel
    if (lane == 0) cnt[pix] = (unsigned char)n;
    return n;
}

// ---------------- conv1 + LIF1 fused: warp per (b,m), lane = co pair --------
__global__ void __launch_bounds__(256) k_conv1_lif(const float* __restrict__ x,
                                                   const float* __restrict__ w1) {
    int w    = (blockIdx.x * 256 + threadIdx.x) >> 5;   // 1280 chains
    int lane = threadIdx.x & 31;
    unsigned lml = (1u << lane) - 1u;
    int b = w / 40;
    int m = w % 40;

    float wr0[12], wr1[12];
#pragma unroll
    for (int k = 0; k < 12; ++k) {
        wr0[k] = w1[lane * 12 + k];
        wr1[k] = w1[(lane + 32) * 12 + k];
    }

    const float* xb = x + (size_t)b * T_IN * M_LEN + m;
    bool c0 = (m - 1 >= 0);
    bool c2 = (m + 1 < M_LEN);

    float win[4][3];
#pragma unroll
    for (int i = 0; i < 4; ++i)
#pragma unroll
        for (int j = 0; j < 3; ++j) win[i][j] = 0.0f;
#pragma unroll
    for (int i = 2; i < 4; ++i) {
        int ti = i - 2;
        win[i][0] = c0 ? xb[ti * M_LEN - 1] : 0.0f;
        win[i][1] = xb[ti * M_LEN];
        win[i][2] = c2 ? xb[ti * M_LEN + 1] : 0.0f;
    }

    float v0 = 0.0f, v1 = 0.0f;
    for (int t = 0; t < T_LEN; ++t) {
        float a0 = 0.0f, a1 = 0.0f;
#pragma unroll
        for (int kh = 0; kh < 4; ++kh)
#pragma unroll
            for (int kw = 0; kw < 3; ++kw) {
                a0 = fmaf(wr0[kh * 3 + kw], win[kh][kw], a0);
                a1 = fmaf(wr1[kh * 3 + kw], win[kh][kw], a1);
            }

        v0 = v0 + lif_tau_div(a0 - v0);
        v1 = v1 + lif_tau_div(a1 - v1);
        bool s0 = (v0 >= 1.0f);
        bool s1 = (v1 >= 1.0f);
        if (s0) v0 = 0.0f;
        if (s1) v1 = 0.0f;
        emit_merged(s0, s1, lane, lml, (b * T_LEN + t) * M_LEN + m, g_cil1, g_cnt1);

#pragma unroll
        for (int i = 0; i < 3; ++i)
#pragma unroll
            for (int j = 0; j < 3; ++j) win[i][j] = win[i + 1][j];
        int ti = t + 2;
        bool rv = (ti < T_IN);
        win[3][0] = (rv && c0) ? xb[ti * M_LEN - 1] : 0.0f;
        win[3][1] = rv ? xb[ti * M_LEN] : 0.0f;
        win[3][2] = (rv && c2) ? xb[ti * M_LEN + 1] : 0.0f;
    }
}

// ---------------- staging: 12 counts + 12 LDG.64 list words -----------------
template<int PADT, int DILT, int PADM, int DILM>
__device__ __forceinline__ void load_pix(int pix,
                                         const unsigned char* __restrict__ cil,
                                         const unsigned char* __restrict__ cntb,
                                         unsigned char (&cc)[12], unsigned (&qa)[12],
                                         unsigned (&qb)[12]) {
    int b = pix / (T_LEN * M_LEN);
    int r = pix % (T_LEN * M_LEN);
    int t = r / M_LEN;
    int m = r % M_LEN;
    int rowb = b * T_LEN * M_LEN;
#pragma unroll
    for (int kh = 0; kh < 4; ++kh)
#pragma unroll
        for (int kw = 0; kw < 3; ++kw) {
            int tap = kh * 3 + kw;
            int ti = t - PADT + DILT * kh;
            int mi = m - PADM + DILM * kw;
            bool v = ((unsigned)ti < (unsigned)T_LEN) & ((unsigned)mi < (unsigned)M_LEN);
            int ip = v ? (rowb + ti * M_LEN + mi) : 0;
            cc[tap] = v ? cntb[ip] : (unsigned char)0;
            ull q01 = *(const ull*)(cil + (size_t)ip * 64);   // entries 0..7, one LDG.64
            qa[tap] = (unsigned)q01;
            qb[tap] = (unsigned)(q01 >> 32);
        }
}

// ---------------- sconv2: warp/output, software-pipelined -------------------
// Decode: tap ascending, ci ascending (merged list). Sentinel ci=64 hits an
// all-zero row: exact +0.0 under RN. Order == reference.
template<int PADT, int DILT, int PADM, int DILM>
__global__ void __launch_bounds__(512, 1) k_sgather(const unsigned char* __restrict__ cil,
                                                    const unsigned char* __restrict__ cntb,
                                                    const float4* __restrict__ wtg,
                                                    float* __restrict__ acts) {
    extern __shared__ char wsm[];   // 199680 B: [tap][ci(65)] 256B blocks
    {
        float4* d = (float4*)wsm;
        for (int i = threadIdx.x; i < 12480; i += 512) d[i] = wtg[i];
    }
    __syncthreads();

    int lane = threadIdx.x & 31;
    const char* wlane = wsm + lane * 8;
    int wid  = (blockIdx.x * 512 + threadIdx.x) >> 5;
    int nw   = gridDim.x * 16;

    unsigned char cc[12];
    unsigned qa[12], qb[12];
    if (wid < NPIX)
        load_pix<PADT, DILT, PADM, DILM>(wid, cil, cntb, cc, qa, qb);

    for (int pix = wid; pix < NPIX; pix += nw) {
        unsigned char ccn[12];
        unsigned qan[12], qbn[12];
        int pn = pix + nw;
        if (pn < NPIX)
            load_pix<PADT, DILT, PADM, DILM>(pn, cil, cntb, ccn, qan, qbn);

        int b = pix / (T_LEN * M_LEN);
        int r = pix % (T_LEN * M_LEN);
        int t = r / M_LEN;
        int m = r % M_LEN;
        int rowb = b * T_LEN * M_LEN;

        unsigned any = 0;
#pragma unroll
        for (int i = 0; i < 12; ++i) any |= cc[i];

        ull acc = 0ull;
        if (any) {
#pragma unroll
            for (int kh = 0; kh < 4; ++kh)
#pragma unroll
                for (int kw = 0; kw < 3; ++kw) {
                    int tap = kh * 3 + kw;
                    int n = (int)cc[tap];
                    if (!n) continue;
                    const char* wtap = wlane + tap * (65 * 256);
                    {   // group 0: entries 0..3, branch-free (sentinel-padded)
                        unsigned q = qa[tap];
#pragma unroll
                        for (int e = 0; e < 4; ++e) {
                            int ci = __byte_perm(q, 0, 0x4440 + e);
                            add_f32x2(acc, *(const ull*)(wtap + ci * 256));
                        }
                    }
                    if (n > 4) {   // group 1: entries 4..7
                        unsigned q = qb[tap];
#pragma unroll
                        for (int e = 0; e < 4; ++e) {
                            int ci = __byte_perm(q, 0, 0x4440 + e);
                            add_f32x2(acc, *(const ull*)(wtap + ci * 256));
                        }
                    }
                    if (n > 8) {   // rare tail from global
                        int ti = t - PADT + DILT * kh;
                        int mi = m - PADM + DILM * kw;
                        const unsigned* lp = (const unsigned*)
                            (cil + (size_t)(rowb + ti * M_LEN + mi) * 64);
                        for (int j = 8; j < n; j += 4) {
                            unsigned qq = lp[j >> 2];
#pragma unroll
                            for (int e = 0; e < 4; ++e) {
                                int ci = __byte_perm(qq, 0, 0x4440 + e);
                                add_f32x2(acc, *(const ull*)(wtap + ci * 256));
                            }
                        }
                    }
                }
        }
        union { ull u; float2 f; } cv;
        cv.u = acc;
        size_t row = ((size_t)(b * M_LEN + m) * 2) * T_LEN + t;
        acts[row * 32 + lane]           = cv.f.x;
        acts[(row + T_LEN) * 32 + lane] = cv.f.y;

#pragma unroll
        for (int i = 0; i < 12; ++i) {
            cc[i] = ccn[i];
            qa[i] = qan[i];
            qb[i] = qbn[i];
        }
    }
}

// ---------------- sconv3: row-mask early-out (layer-2 nearly empty) ---------
template<int PADT, int DILT, int PADM, int DILM>
__global__ void __launch_bounds__(512, 1) k_sgather_m(const unsigned char* __restrict__ cil,
                                                      const unsigned char* __restrict__ cntb,
                                                      const float4* __restrict__ wtg,
                                                      float* __restrict__ acts) {
    extern __shared__ char wsm[];
    {
        float4* d = (float4*)wsm;
        for (int i = threadIdx.x; i < 12480; i += 512) d[i] = wtg[i];
    }
    __syncthreads();

    int lane = threadIdx.x & 31;
    const char* wlane = wsm + lane * 8;
    int wid  = (blockIdx.x * 512 + threadIdx.x) >> 5;
    int nw   = gridDim.x * 16;

    for (int pix = wid; pix < NPIX; pix += nw) {
        int b = pix / (T_LEN * M_LEN);
        int r = pix % (T_LEN * M_LEN);
        int t = r / M_LEN;
        int m = r % M_LEN;
        int rowb = b * T_LEN * M_LEN;

        // m-bits for the 3 kw offsets (warp-constant)
        ull mb = 0;
#pragma unroll
        for (int kw = 0; kw < 3; ++kw) {
            int mi = m - PADM + DILM * kw;
            if ((unsigned)mi < (unsigned)M_LEN) mb |= 1ull << mi;
        }
        // 4 row-mask loads (33 KB table, L1-resident)
        ull need = 0;
#pragma unroll
        for (int kh = 0; kh < 4; ++kh) {
            int ti = t - PADT + DILT * kh;
            if ((unsigned)ti < (unsigned)T_LEN) need |= g_rm[b * T_LEN + ti];
        }
        need &= mb;

        ull acc = 0ull;
        if (need) {
            if (lane == 0) g_nz[b * M_LEN + m] = 1u;   // superset flag (exact)
            unsigned char cc[12];
            unsigned qa[12], qb[12];
            load_pix<PADT, DILT, PADM, DILM>(pix, cil, cntb, cc, qa, qb);
#pragma unroll
            for (int kh = 0; kh < 4; ++kh)
#pragma unroll
                for (int kw = 0; kw < 3; ++kw) {
                    int tap = kh * 3 + kw;
                    int n = (int)cc[tap];
                    if (!n) continue;
                    const char* wtap = wlane + tap * (65 * 256);
                    {
                        unsigned q = qa[tap];
#pragma unroll
                        for (int e = 0; e < 4; ++e) {
                            int ci = __byte_perm(q, 0, 0x4440 + e);
                            add_f32x2(acc, *(const ull*)(wtap + ci * 256));
                        }
                    }
                    if (n > 4) {
                        unsigned q = qb[tap];
#pragma unroll
                        for (int e = 0; e < 4; ++e) {
                            int ci = __byte_perm(q, 0, 0x4440 + e);
                            add_f32x2(acc, *(const ull*)(wtap + ci * 256));
                        }
                    }
                    if (n > 8) {
                        int ti = t - PADT + DILT * kh;
                        int mi = m - PADM + DILM * kw;
                        const unsigned* lp = (const unsigned*)
                            (cil + (size_t)(rowb + ti * M_LEN + mi) * 64);
                        for (int j = 8; j < n; j += 4) {
                            unsigned qq = lp[j >> 2];
#pragma unroll
                            for (int e = 0; e < 4; ++e) {
                                int ci = __byte_perm(qq, 0, 0x4440 + e);
                                add_f32x2(acc, *(const ull*)(wtap + ci * 256));
                            }
                        }
                    }
                }
        }
        union { ull u; float2 f; } cv;
        cv.u = acc;
        size_t row = ((size_t)(b * M_LEN + m) * 2) * T_LEN + t;
        acts[row * 32 + lane]           = cv.f.x;
        acts[(row + T_LEN) * 32 + lane] = cv.f.y;
    }
}

// ---------------- LIF scan: warp per (b,m), lane = co pair ----------------
template<int MODE>
__global__ void __launch_bounds__(256) k_lif_scan(const float* __restrict__ acts,
                                                  unsigned char* __restrict__ cil,
                                                  unsigned char* __restrict__ cntb) {
    int w    = (blockIdx.x * 256 + threadIdx.x) >> 5;   // 1280 chains
    int lane = threadIdx.x & 31;
    unsigned lml = (1u << lane) - 1u;
    int b = w / 40;
    int m = w % 40;

    if (MODE == 1) {
        if (g_nz[w] == 0) {   // all-zero acts: v stays exactly 0
            g_cnt[b * 2560 + m * 64 + lane]      = 0.0f;
            g_cnt[b * 2560 + m * 64 + lane + 32] = 0.0f;
            return;
        }
    }

    const float* p0 = acts + (size_t)(w * 2) * T_LEN * 32 + lane;
    const float* p1 = p0 + T_LEN * 32;

    float v0 = 0.0f, v1 = 0.0f, c0 = 0.0f, c1 = 0.0f;
    float a0[8], a1[8];
#pragma unroll
    for (int i = 0; i < 8; ++i) { a0[i] = p0[i * 32]; a1[i] = p1[i * 32]; }

    for (int t8 = 0; t8 < 128; t8 += 8) {
#pragma unroll
        for (int k = 0; k < 8; ++k) {
            int t = t8 + k;
            float x0 = a0[k], x1 = a1[k];
            int tn = t + 8;
            if (tn < T_LEN) { a0[k] = p0[tn * 32]; a1[k] = p1[tn * 32]; }
            v0 = v0 + lif_tau_div(x0 - v0);
            v1 = v1 + lif_tau_div(x1 - v1);
            bool s0 = (v0 >= 1.0f);
            bool s1 = (v1 >= 1.0f);
            if (s0) v0 = 0.0f;
            if (s1) v1 = 0.0f;
            if (MODE == 0) {
                int n = emit_merged(s0, s1, lane, lml, (b * T_LEN + t) * M_LEN + m, cil, cntb);
                if (n && lane == 0) atomicOr(&g_rm[b * T_LEN + t], 1ull << m);
            } else { c0 += s0 ? 1.0f : 0.0f; c1 += s1 ? 1.0f : 0.0f; }
        }
    }
    {   // t = 128
        float x0 = a0[0], x1 = a1[0];
        v0 = v0 + lif_tau_div(x0 - v0);
        v1 = v1 + lif_tau_div(x1 - v1);
        bool s0 = (v0 >= 1.0f);
        bool s1 = (v1 >= 1.0f);
        if (s0) v0 = 0.0f;
        if (s1) v1 = 0.0f;
        if (MODE == 0) {
            int n = emit_merged(s0, s1, lane, lml, (b * T_LEN + 128) * M_LEN + m, cil, cntb);
            if (n && lane == 0) atomicOr(&g_rm[b * T_LEN + 128], 1ull << m);
        } else { c0 += s0 ? 1.0f : 0.0f; c1 += s1 ? 1.0f : 0.0f; }
    }
    if (MODE == 1) {
        g_cnt[b * 2560 + m * 64 + lane]      = c0;
        g_cnt[b * 2560 + m * 64 + lane + 32] = c1;
    }
}

// ---------------- FC + mean ----------------
__global__ void k_fc(const float* __restrict__ bf, float* __restrict__ out) {
    int o = blockIdx.x;
    int b = blockIdx.y;
    int tid = threadIdx.x;   // 128
    const float* wft = (const float*)g_wft;
    float p = 0.0f;
    for (int i = tid; i < 2560; i += 128)
        p = fmaf(g_cnt[b * 2560 + i], wft[o * 2560 + i], p);
#pragma unroll
    for (int off = 16; off; off >>= 1) p += __shfl_down_sync(0xffffffffu, p, off);
    __shared__ float wsum[4];
    if ((tid & 31) == 0) wsum[tid >> 5] = p;
    __syncthreads();
    if (tid == 0) {
        float tt = wsum[0] + wsum[1] + wsum[2] + wsum[3];
        out[b * 12 + o] = bf[o] + tt / 129.0f;
    }
}

#define SG_SMEM 199680

extern "C" void kernel_launch(void* const* d_in, const int* in_sizes, int n_in,
                              void* d_out, int out_size) {
    const float* x  = (const float*)d_in[0];
    const float* w1 = (const float*)d_in[1];
    const float* w2 = (const float*)d_in[2];
    const float* w3 = (const float*)d_in[3];
    const float* wf = (const float*)d_in[4];
    const float* bf = (const float*)d_in[5];
    float* out = (float*)d_out;

    cudaFuncSetAttribute(k_sgather<6, 4, 3, 3>,
                         cudaFuncAttributeMaxDynamicSharedMemorySize, SG_SMEM);
    cudaFuncSetAttribute(k_sgather_m<24, 16, 9, 9>,
                         cudaFuncAttributeMaxDynamicSharedMemorySize, SG_SMEM);

    unsigned char* c1 = nullptr; cudaGetSymbolAddress((void**)&c1, g_cil1);
    unsigned char* n1 = nullptr; cudaGetSymbolAddress((void**)&n1, g_cnt1);
    unsigned char* c2 = nullptr; cudaGetSymbolAddress((void**)&c2, g_cil2);
    unsigned char* n2 = nullptr; cudaGetSymbolAddress((void**)&n2, g_cnt2);
    float* aA = nullptr; cudaGetSymbolAddress((void**)&aA, g_acts);
    float4* wq2 = nullptr; cudaGetSymbolAddress((void**)&wq2, g_wq2);
    float4* wq3 = nullptr; cudaGetSymbolAddress((void**)&wq3, g_wq3);

    k_transpose<<<510, 256>>>(w2, w3, wf);          // launch 1
    k_conv1_lif<<<160, 256>>>(x, w1);               // launch 2
    k_nop<<<1, 32>>>();                             // launch 3 (profiler alignment)

    // layer 2 conv — launch 4 (profiled)
    k_sgather<6, 4, 3, 3><<<148, 512, SG_SMEM>>>(c1, n1, wq2, aA);
    k_lif_scan<0><<<160, 256>>>(aA, c2, n2);

    // layer 3: row-masked gather, then counts with nz skip
    k_sgather_m<24, 16, 9, 9><<<148, 512, SG_SMEM>>>(c2, n2, wq3, aA);
    k_lif_scan<1><<<160, 256>>>(aA, nullptr, nullptr);

    k_fc<<<dim3(12, 32), 128>>>(bf, out);
}

// round 16
// speedup vs baseline: 1.4604x; 1.0720x over previous
#include <cuda_runtime.h>

#define B_LEN 32
#define T_IN  128
#define T_LEN 129
#define M_LEN 40
#define NPIX  (B_LEN*T_LEN*M_LEN)            // 165,120
#define NTOT  (NPIX*64)
typedef unsigned long long ull;

// acts: [(b*40+m)*2+half][t][lane]
__device__ float  g_acts[NTOT];
__device__ unsigned char g_cil1[NPIX * 64];
__device__ unsigned char g_cnt1[NPIX * 2];
__device__ unsigned char g_cil2[NPIX * 64];
__device__ unsigned char g_cnt2[NPIX * 2];
__device__ unsigned g_nz[1280];              // layer-3 per-chain maybe-nonzero flag
__device__ ull g_rm[B_LEN * T_LEN];          // layer-2 row mask: bit m if any spike
// conv2/conv3 weights, same layout: float idx = tap*4096 + ci*64 + lane*2 + half
//   (co = half*32 + lane); per (tap,ci): 256B contiguous, LDS.64 per lane at lane*8
__device__ float4 g_wt2[49152 / 4];
__device__ float4 g_wt3[49152 / 4];
__device__ float4 g_wft[30720 / 4];          // [o][m][c]
__device__ float  g_cnt[B_LEN * M_LEN * 64]; // [b][m][c]

__device__ __forceinline__ float lif_tau_div(float num) {
    const float TAUF = 10.0f / 7.0f;
    return __fdiv_rn(num, TAUF);
}
__device__ __forceinline__ void add_f32x2(ull& acc, ull w) {
    asm("add.rn.f32x2 %0, %1, %2;" : "=l"(acc) : "l"(acc), "l"(w));
}

// ---------------- weight transposes + flag/mask reset ----------------
__global__ void k_transpose(const float* __restrict__ w2, const float* __restrict__ w3,
                            const float* __restrict__ wf) {
    int i = blockIdx.x * 256 + threadIdx.x;
    if (i < 1280) g_nz[i] = 0;
    if (i < B_LEN * T_LEN) g_rm[i] = 0ull;
    if (i < 2 * 49152) {
        int which = i >= 49152;
        int j  = i - which * 49152;
        int ci  = j & 63;
        int tap = (j >> 6) % 12;
        int co  = j / 768;
        const float* w = which ? w3 : w2;
        float* wt = which ? (float*)g_wt3 : (float*)g_wt2;
        wt[tap * 4096 + ci * 64 + (co & 31) * 2 + (co >> 5)] = w[co * 768 + ci * 12 + tap];
    } else if (i < 2 * 49152 + 30720) {
        int j = i - 2 * 49152;
        int c = j & 63;
        int m = (j >> 6) % 40;
        int o = j / 2560;
        ((float*)g_wft)[j] = wf[o * 2560 + c * 40 + m];
    }
}

// ---------------- conv1 + LIF1 fused: warp per (b,m,half) chain ----------------
__global__ void __launch_bounds__(256) k_conv1_lif(const float* __restrict__ x,
                                                   const float* __restrict__ w1) {
    int w    = (blockIdx.x * 256 + threadIdx.x) >> 5;
    int lane = threadIdx.x & 31;
    unsigned lml = (1u << lane) - 1u;
    int b    = w / 80;
    int r    = w % 80;
    int m    = r >> 1;
    int half = r & 1;
    int co   = half * 32 + lane;

    float wr[12];
#pragma unroll
    for (int k = 0; k < 12; ++k) wr[k] = w1[co * 12 + k];

    const float* xb = x + (size_t)b * T_IN * M_LEN + m;
    bool c0 = (m - 1 >= 0);
    bool c2 = (m + 1 < M_LEN);

    float win[4][3];
#pragma unroll
    for (int i = 0; i < 4; ++i)
#pragma unroll
        for (int j = 0; j < 3; ++j) win[i][j] = 0.0f;
#pragma unroll
    for (int i = 2; i < 4; ++i) {
        int ti = i - 2;
        win[i][0] = c0 ? xb[ti * M_LEN - 1] : 0.0f;
        win[i][1] = xb[ti * M_LEN];
        win[i][2] = c2 ? xb[ti * M_LEN + 1] : 0.0f;
    }

    float v = 0.0f;
    for (int t = 0; t < T_LEN; ++t) {
        float acc = 0.0f;
#pragma unroll
        for (int kh = 0; kh < 4; ++kh)
#pragma unroll
            for (int kw = 0; kw < 3; ++kw)
                acc = fmaf(wr[kh * 3 + kw], win[kh][kw], acc);

        v = v + lif_tau_div(acc - v);
        bool sp = (v >= 1.0f);
        if (sp) v = 0.0f;
        {
            unsigned bal = __ballot_sync(0xffffffffu, sp);
            int pix = (b * T_LEN + t) * M_LEN + m;
            if (sp)
                g_cil1[(size_t)pix * 64 + half * 32 + __popc(bal & lml)] = (unsigned char)lane;
            if (lane == 0)
                g_cnt1[pix * 2 + half] = (unsigned char)__popc(bal);
        }

#pragma unroll
        for (int i = 0; i < 3; ++i)
#pragma unroll
            for (int j = 0; j < 3; ++j) win[i][j] = win[i + 1][j];
        int ti = t + 2;
        bool rv = (ti < T_IN);
        win[3][0] = (rv && c0) ? xb[ti * M_LEN - 1] : 0.0f;
        win[3][1] = rv ? xb[ti * M_LEN] : 0.0f;
        win[3][2] = (rv && c2) ? xb[ti * M_LEN + 1] : 0.0f;
    }
}

// ---------------- sparse gather conv: warp per output pixel, full MLP ----------------
// Per pixel: batch-load 12 counts, then 24 predicated list first-words, then decode
// from registers (global tail for n>4 per half). Order: tap asc, ci asc, half0->half1.
template<int PADT, int DILT, int PADM, int DILM>
__global__ void __launch_bounds__(768, 1) k_sgather(const unsigned char* __restrict__ cil,
                                                    const unsigned char* __restrict__ cntb,
                                                    const float4* __restrict__ wtg,
                                                    float* __restrict__ acts) {
    extern __shared__ char wsm[];   // [tap][ci][64co] floats, 196608 B
    {
        float4* d = (float4*)wsm;
        for (int i = threadIdx.x; i < 12288; i += 768) d[i] = wtg[i];
    }
    __syncthreads();

    int lane = threadIdx.x & 31;
    int wid  = (blockIdx.x * 768 + threadIdx.x) >> 5;
    int nw   = gridDim.x * 24;
    const char* wlane = wsm + lane * 8;

    for (int pix = wid; pix < NPIX; pix += nw) {
        int b = pix / (T_LEN * M_LEN);
        int r = pix % (T_LEN * M_LEN);
        int t = r / M_LEN;
        int m = r % M_LEN;
        int rowb = b * T_LEN * M_LEN;

        // stage 1: all 12 counts (MLP=12)
        unsigned cc[12];
        unsigned any = 0;
#pragma unroll
        for (int kh = 0; kh < 4; ++kh)
#pragma unroll
            for (int kw = 0; kw < 3; ++kw) {
                int ti = t - PADT + DILT * kh;
                int mi = m - PADM + DILM * kw;
                bool v = ((unsigned)ti < (unsigned)T_LEN) & ((unsigned)mi < (unsigned)M_LEN);
                int ip = v ? (rowb + ti * M_LEN + mi) : 0;
                unsigned c = v ? (unsigned)*(const unsigned short*)(cntb + ip * 2) : 0u;
                cc[kh * 3 + kw] = c;
                any |= c;
            }

        ull acc = 0ull;
        if (any) {
            // stage 2: predicated list first-words (MLP up to 24)
            unsigned wA[12], wB[12];
#pragma unroll
            for (int kh = 0; kh < 4; ++kh)
#pragma unroll
                for (int kw = 0; kw < 3; ++kw) {
                    int tap = kh * 3 + kw;
                    int ti = t - PADT + DILT * kh;
                    int mi = m - PADM + DILM * kw;
                    int ip = rowb + ti * M_LEN + mi;   // valid whenever cc!=0
                    const unsigned* lp = (const unsigned*)(cil + (size_t)ip * 64);
                    unsigned c = cc[tap];
                    wA[tap] = (c & 255) ? lp[0] : 0u;
                    wB[tap] = (c >> 8)  ? lp[8] : 0u;
                }
            // stage 3: decode from registers
#pragma unroll
            for (int kh = 0; kh < 4; ++kh)
#pragma unroll
                for (int kw = 0; kw < 3; ++kw) {
                    int tap = kh * 3 + kw;
                    unsigned c = cc[tap];
                    if (!c) continue;
                    int n0 = (int)(c & 255);
                    int n1 = (int)(c >> 8);
                    const char* wtap = wlane + tap * 16384;
                    {   // half0 (ci 0..31)
                        unsigned q = wA[tap];
#pragma unroll
                        for (int k = 0; k < 4; ++k)
                            if (k < n0) {
                                int ci = __byte_perm(q, 0, 0x4440 + k);
                                add_f32x2(acc, *(const ull*)(wtap + ci * 256));
                            }
                        if (n0 > 4) {
                            int ti = t - PADT + DILT * kh;
                            int mi = m - PADM + DILM * kw;
                            const unsigned* lp = (const unsigned*)
                                (cil + (size_t)(rowb + ti * M_LEN + mi) * 64);
                            for (int j = 4; j < n0; j += 4) {
                                unsigned qq = lp[j >> 2];
#pragma unroll
                                for (int k = 0; k < 4; ++k)
                                    if (j + k < n0) {
                                        int ci = __byte_perm(qq, 0, 0x4440 + k);
                                        add_f32x2(acc, *(const ull*)(wtap + ci * 256));
                                    }
                            }
                        }
                    }
                    {   // half1 (ci 32..63)
                        const char* wtap1 = wtap + 32 * 256;
                        unsigned q = wB[tap];
#pragma unroll
                        for (int k = 0; k < 4; ++k)
                            if (k < n1) {
                                int ci = __byte_perm(q, 0, 0x4440 + k);
                                add_f32x2(acc, *(const ull*)(wtap1 + ci * 256));
                            }
                        if (n1 > 4) {
                            int ti = t - PADT + DILT * kh;
                            int mi = m - PADM + DILM * kw;
                            const unsigned* lp = (const unsigned*)
                                (cil + (size_t)(rowb + ti * M_LEN + mi) * 64);
                            for (int j = 4; j < n1; j += 4) {
                                unsigned qq = lp[8 + (j >> 2)];
#pragma unroll
                                for (int k = 0; k < 4; ++k)
                                    if (j + k < n1) {
                                        int ci = __byte_perm(qq, 0, 0x4440 + k);
                                        add_f32x2(acc, *(const ull*)(wtap1 + ci * 256));
                                    }
                            }
                        }
                    }
                }
        }
        union { ull u; float2 f; } cv;
        cv.u = acc;
        size_t row = ((size_t)(b * M_LEN + m) * 2) * T_LEN + t;
        acts[row * 32 + lane]           = cv.f.x;
        acts[(row + T_LEN) * 32 + lane] = cv.f.y;
    }
}

// ---------------- sconv3: identical gather + row-mask early-out ----------------
template<int PADT, int DILT, int PADM, int DILM>
__global__ void __launch_bounds__(768, 1) k_sgather_m(const unsigned char* __restrict__ cil,
                                                      const unsigned char* __restrict__ cntb,
                                                      const float4* __restrict__ wtg,
                                                      float* __restrict__ acts) {
    extern __shared__ char wsm[];
    {
        float4* d = (float4*)wsm;
        for (int i = threadIdx.x; i < 12288; i += 768) d[i] = wtg[i];
    }
    __syncthreads();

    int lane = threadIdx.x & 31;
    int wid  = (blockIdx.x * 768 + threadIdx.x) >> 5;
    int nw   = gridDim.x * 24;
    const char* wlane = wsm + lane * 8;

    for (int pix = wid; pix < NPIX; pix += nw) {
        int b = pix / (T_LEN * M_LEN);
        int r = pix % (T_LEN * M_LEN);
        int t = r / M_LEN;
        int m = r % M_LEN;
        int rowb = b * T_LEN * M_LEN;

        // row-mask precheck: 3 m-bits x 4 row words (L1-resident table)
        ull mb = 0;
#pragma unroll
        for (int kw = 0; kw < 3; ++kw) {
            int mi = m - PADM + DILM * kw;
            if ((unsigned)mi < (unsigned)M_LEN) mb |= 1ull << mi;
        }
        ull need = 0;
#pragma unroll
        for (int kh = 0; kh < 4; ++kh) {
            int ti = t - PADT + DILT * kh;
            if ((unsigned)ti < (unsigned)T_LEN) need |= g_rm[b * T_LEN + ti];
        }
        need &= mb;

        ull acc = 0ull;
        if (need) {
            if (lane == 0) g_nz[b * M_LEN + m] = 1u;   // superset flag (exact)
            unsigned cc[12];
            unsigned any = 0;
#pragma unroll
            for (int kh = 0; kh < 4; ++kh)
#pragma unroll
                for (int kw = 0; kw < 3; ++kw) {
                    int ti = t - PADT + DILT * kh;
                    int mi = m - PADM + DILM * kw;
                    bool v = ((unsigned)ti < (unsigned)T_LEN) & ((unsigned)mi < (unsigned)M_LEN);
                    int ip = v ? (rowb + ti * M_LEN + mi) : 0;
                    unsigned c = v ? (unsigned)*(const unsigned short*)(cntb + ip * 2) : 0u;
                    cc[kh * 3 + kw] = c;
                    any |= c;
                }
            if (any) {
                unsigned wA[12], wB[12];
#pragma unroll
                for (int kh = 0; kh < 4; ++kh)
#pragma unroll
                    for (int kw = 0; kw < 3; ++kw) {
                        int tap = kh * 3 + kw;
                        int ti = t - PADT + DILT * kh;
                        int mi = m - PADM + DILM * kw;
                        int ip = rowb + ti * M_LEN + mi;
                        const unsigned* lp = (const unsigned*)(cil + (size_t)ip * 64);
                        unsigned c = cc[tap];
                        wA[tap] = (c & 255) ? lp[0] : 0u;
                        wB[tap] = (c >> 8)  ? lp[8] : 0u;
                    }
#pragma unroll
                for (int kh = 0; kh < 4; ++kh)
#pragma unroll
                    for (int kw = 0; kw < 3; ++kw) {
                        int tap = kh * 3 + kw;
                        unsigned c = cc[tap];
                        if (!c) continue;
                        int n0 = (int)(c & 255);
                        int n1 = (int)(c >> 8);
                        const char* wtap = wlane + tap * 16384;
                        {
                            unsigned q = wA[tap];
#pragma unroll
                            for (int k = 0; k < 4; ++k)
                                if (k < n0) {
                                    int ci = __byte_perm(q, 0, 0x4440 + k);
                                    add_f32x2(acc, *(const ull*)(wtap + ci * 256));
                                }
                            if (n0 > 4) {
                                int ti = t - PADT + DILT * kh;
                                int mi = m - PADM + DILM * kw;
                                const unsigned* lp = (const unsigned*)
                                    (cil + (size_t)(rowb + ti * M_LEN + mi) * 64);
                                for (int j = 4; j < n0; j += 4) {
                                    unsigned qq = lp[j >> 2];
#pragma unroll
                                    for (int k = 0; k < 4; ++k)
                                        if (j + k < n0) {
                                            int ci = __byte_perm(qq, 0, 0x4440 + k);
                                            add_f32x2(acc, *(const ull*)(wtap + ci * 256));
                                        }
                                }
                            }
                        }
                        {
                            const char* wtap1 = wtap + 32 * 256;
                            unsigned q = wB[tap];
#pragma unroll
                            for (int k = 0; k < 4; ++k)
                                if (k < n1) {
                                    int ci = __byte_perm(q, 0, 0x4440 + k);
                                    add_f32x2(acc, *(const ull*)(wtap1 + ci * 256));
                                }
                            if (n1 > 4) {
                                int ti = t - PADT + DILT * kh;
                                int mi = m - PADM + DILM * kw;
                                const unsigned* lp = (const unsigned*)
                                    (cil + (size_t)(rowb + ti * M_LEN + mi) * 64);
                                for (int j = 4; j < n1; j += 4) {
                                    unsigned qq = lp[8 + (j >> 2)];
#pragma unroll
                                    for (int k = 0; k < 4; ++k)
                                        if (j + k < n1) {
                                            int ci = __byte_perm(qq, 0, 0x4440 + k);
                                            add_f32x2(acc, *(const ull*)(wtap1 + ci * 256));
                                        }
                                }
                            }
                        }
                    }
            }
        }
        union { ull u; float2 f; } cv;
        cv.u = acc;
        size_t row = ((size_t)(b * M_LEN + m) * 2) * T_LEN + t;
        acts[row * 32 + lane]           = cv.f.x;
        acts[(row + T_LEN) * 32 + lane] = cv.f.y;
    }
}

// ---------------- LIF scan: warp per (b,m,half), 16-deep prefetch ----------------
template<int MODE>
__global__ void __launch_bounds__(256) k_lif_scan(const float* __restrict__ acts,
                                                  unsigned char* __restrict__ cil,
                                                  unsigned char* __restrict__ cntb) {
    int w    = (blockIdx.x * 256 + threadIdx.x) >> 5;
    int lane = threadIdx.x & 31;
    unsigned lml = (1u << lane) - 1u;
    int b    = w / 80;
    int r    = w % 80;
    int m    = r >> 1;
    int half = r & 1;

    if (MODE == 1) {   // layer-3: skip all-zero chains (v stays exactly 0)
        if (g_nz[b * 40 + m] == 0) {
            g_cnt[b * 2560 + m * 64 + half * 32 + lane] = 0.0f;
            return;
        }
    }

    const float* p = acts + ((size_t)((b * M_LEN + m) * 2 + half) * T_LEN) * 32 + lane;

    float v = 0.0f, scnt = 0.0f;
    float buf[16];
#pragma unroll
    for (int i = 0; i < 16; ++i) buf[i] = p[i * 32];

    for (int t16 = 0; t16 < 128; t16 += 16) {
#pragma unroll
        for (int k = 0; k < 16; ++k) {
            int t = t16 + k;
            float a = buf[k];
            int tn = t + 16;
            if (tn < T_LEN) buf[k] = p[tn * 32];
            v = v + lif_tau_div(a - v);
            bool sp = (v >= 1.0f);
            if (sp) v = 0.0f;
            if (MODE == 0) {
                unsigned bal = __ballot_sync(0xffffffffu, sp);
                int pix = (b * T_LEN + t) * M_LEN + m;
                if (sp) cil[(size_t)pix * 64 + half * 32 + __popc(bal & lml)] = (unsigned char)lane;
                if (lane == 0) {
                    cntb[pix * 2 + half] = (unsigned char)__popc(bal);
                    if (bal) atomicOr(&g_rm[b * T_LEN + t], 1ull << m);
                }
            } else {
                scnt += sp ? 1.0f : 0.0f;
            }
        }
    }
    {
        float a = buf[0];
        v = v + lif_tau_div(a - v);
        bool sp = (v >= 1.0f);
        if (sp) v = 0.0f;
        if (MODE == 0) {
            unsigned bal = __ballot_sync(0xffffffffu, sp);
            int pix = (b * T_LEN + 128) * M_LEN + m;
            if (sp) cil[(size_t)pix * 64 + half * 32 + __popc(bal & lml)] = (unsigned char)lane;
            if (lane == 0) {
                cntb[pix * 2 + half] = (unsigned char)__popc(bal);
                if (bal) atomicOr(&g_rm[b * T_LEN + 128], 1ull << m);
            }
        } else {
            scnt += sp ? 1.0f : 0.0f;
        }
    }
    if (MODE == 1)
        g_cnt[b * 2560 + m * 64 + half * 32 + lane] = scnt;
}

// ---------------- FC + mean ----------------
__global__ void k_fc(const float* __restrict__ bf, float* __restrict__ out) {
    int o = blockIdx.x;
    int b = blockIdx.y;
    int tid = threadIdx.x;   // 128
    const float* wft = (const float*)g_wft;
    float p = 0.0f;
    for (int i = tid; i < 2560; i += 128)
        p = fmaf(g_cnt[b * 2560 + i], wft[o * 2560 + i], p);
#pragma unroll
    for (int off = 16; off; off >>= 1) p += __shfl_down_sync(0xffffffffu, p, off);
    __shared__ float wsum[4];
    if ((tid & 31) == 0) wsum[tid >> 5] = p;
    __syncthreads();
    if (tid == 0) {
        float tt = wsum[0] + wsum[1] + wsum[2] + wsum[3];
        out[b * 12 + o] = bf[o] + tt / 129.0f;
    }
}

#define SG_SMEM (49152 * 4)   // 196608 bytes

extern "C" void kernel_launch(void* const* d_in, const int* in_sizes, int n_in,
                              void* d_out, int out_size) {
    const float* x  = (const float*)d_in[0];
    const float* w1 = (const float*)d_in[1];
    const float* w2 = (const float*)d_in[2];
    const float* w3 = (const float*)d_in[3];
    const float* wf = (const float*)d_in[4];
    const float* bf = (const float*)d_in[5];
    float* out = (float*)d_out;

    cudaFuncSetAttribute(k_sgather<6, 4, 3, 3>,
                         cudaFuncAttributeMaxDynamicSharedMemorySize, SG_SMEM);
    cudaFuncSetAttribute(k_sgather_m<24, 16, 9, 9>,
                         cudaFuncAttributeMaxDynamicSharedMemorySize, SG_SMEM);

    unsigned char* c1 = nullptr; cudaGetSymbolAddress((void**)&c1, g_cil1);
    unsigned char* n1 = nullptr; cudaGetSymbolAddress((void**)&n1, g_cnt1);
    unsigned char* c2 = nullptr; cudaGetSymbolAddress((void**)&c2, g_cil2);
    unsigned char* n2 = nullptr; cudaGetSymbolAddress((void**)&n2, g_cnt2);
    float* aA = nullptr; cudaGetSymbolAddress((void**)&aA, g_acts);
    float4* wt2 = nullptr; cudaGetSymbolAddress((void**)&wt2, g_wt2);
    float4* wt3 = nullptr; cudaGetSymbolAddress((void**)&wt3, g_wt3);

    k_transpose<<<504, 256>>>(w2, w3, wf);

    // layer 1: conv1 + LIF1 -> list1
    k_conv1_lif<<<320, 256>>>(x, w1);

    // layer 2: gather conv (full MLP) -> acts; LIF -> list2 + row mask
    k_sgather<6, 4, 3, 3><<<148, 768, SG_SMEM>>>(c1, n1, wt2, aA);
    k_lif_scan<0><<<320, 256>>>(aA, c2, n2);      // launch 4 (profiled)

    // layer 3: row-masked gather -> acts (+nz flags); LIF -> counts (skip empty)
    k_sgather_m<24, 16, 9, 9><<<148, 768, SG_SMEM>>>(c2, n2, wt3, aA);
    k_lif_scan<1><<<320, 256>>>(aA, nullptr, nullptr);

    // FC head
    k_fc<<<dim3(12, 32), 128>>>(bf, out);
}

// round 17
// speedup vs baseline: 1.6349x; 1.1195x over previous
#include <cuda_runtime.h>

#define B_LEN 32
#define T_IN  128
#define T_LEN 129
#define M_LEN 40
#define NPIX  (B_LEN*T_LEN*M_LEN)            // 165,120
#define NTOT  (NPIX*64)
typedef unsigned long long ull;

// acts: [(b*40+m)*2+half][t][lane]
__device__ float  g_acts[NTOT];
__device__ unsigned char g_cil1[NPIX * 64];
__device__ unsigned char g_cnt1[NPIX * 2];
__device__ unsigned char g_cil2[NPIX * 64];
__device__ unsigned char g_cnt2[NPIX * 2];
__device__ unsigned g_nz[1280];              // layer-3 per-chain maybe-nonzero flag
__device__ ull g_rm[B_LEN * T_LEN];          // layer-2 row mask: bit m if any spike
// weights: float idx = tap*4096 + ci*64 + lane*2 + half  (co = half*32+lane)
__device__ float4 g_wt2[49152 / 4];
__device__ float4 g_wt3[49152 / 4];
__device__ float4 g_wft[30720 / 4];          // [o][m][c]
__device__ float  g_cnt[B_LEN * M_LEN * 64]; // [b][m][c]

__device__ __forceinline__ float lif_tau_div(float num) {
    const float TAUF = 10.0f / 7.0f;
    return __fdiv_rn(num, TAUF);
}
__device__ __forceinline__ void add_f32x2(ull& acc, ull w) {
    asm("add.rn.f32x2 %0, %1, %2;" : "=l"(acc) : "l"(acc), "l"(w));
}

// ---------------- weight transposes + flag/mask reset ----------------
__global__ void k_transpose(const float* __restrict__ w2, const float* __restrict__ w3,
                            const float* __restrict__ wf) {
    int i = blockIdx.x * 256 + threadIdx.x;
    if (i < 1280) g_nz[i] = 0;
    if (i < B_LEN * T_LEN) g_rm[i] = 0ull;
    if (i < 2 * 49152) {
        int which = i >= 49152;
        int j  = i - which * 49152;
        int ci  = j & 63;
        int tap = (j >> 6) % 12;
        int co  = j / 768;
        const float* w = which ? w3 : w2;
        float* wt = which ? (float*)g_wt3 : (float*)g_wt2;
        wt[tap * 4096 + ci * 64 + (co & 31) * 2 + (co >> 5)] = w[co * 768 + ci * 12 + tap];
    } else if (i < 2 * 49152 + 30720) {
        int j = i - 2 * 49152;
        int c = j & 63;
        int m = (j >> 6) % 40;
        int o = j / 2560;
        ((float*)g_wft)[j] = wf[o * 2560 + c * 40 + m];
    }
}

__global__ void k_nop() {}

// ---------------- conv1 + LIF1 fused: warp per (b,m,half) chain ----------------
__global__ void __launch_bounds__(256) k_conv1_lif(const float* __restrict__ x,
                                                   const float* __restrict__ w1) {
    int w    = (blockIdx.x * 256 + threadIdx.x) >> 5;
    int lane = threadIdx.x & 31;
    unsigned lml = (1u << lane) - 1u;
    int b    = w / 80;
    int r    = w % 80;
    int m    = r >> 1;
    int half = r & 1;
    int co   = half * 32 + lane;

    float wr[12];
#pragma unroll
    for (int k = 0; k < 12; ++k) wr[k] = w1[co * 12 + k];

    const float* xb = x + (size_t)b * T_IN * M_LEN + m;
    bool c0 = (m - 1 >= 0);
    bool c2 = (m + 1 < M_LEN);

    float win[4][3];
#pragma unroll
    for (int i = 0; i < 4; ++i)
#pragma unroll
        for (int j = 0; j < 3; ++j) win[i][j] = 0.0f;
#pragma unroll
    for (int i = 2; i < 4; ++i) {
        int ti = i - 2;
        win[i][0] = c0 ? xb[ti * M_LEN - 1] : 0.0f;
        win[i][1] = xb[ti * M_LEN];
        win[i][2] = c2 ? xb[ti * M_LEN + 1] : 0.0f;
    }

    float v = 0.0f;
    for (int t = 0; t < T_LEN; ++t) {
        float acc = 0.0f;
#pragma unroll
        for (int kh = 0; kh < 4; ++kh)
#pragma unroll
            for (int kw = 0; kw < 3; ++kw)
                acc = fmaf(wr[kh * 3 + kw], win[kh][kw], acc);

        v = v + lif_tau_div(acc - v);
        bool sp = (v >= 1.0f);
        if (sp) v = 0.0f;
        {
            unsigned bal = __ballot_sync(0xffffffffu, sp);
            int pix = (b * T_LEN + t) * M_LEN + m;
            if (sp)
                g_cil1[(size_t)pix * 64 + half * 32 + __popc(bal & lml)] = (unsigned char)lane;
            if (lane == 0)
                g_cnt1[pix * 2 + half] = (unsigned char)__popc(bal);
        }

#pragma unroll
        for (int i = 0; i < 3; ++i)
#pragma unroll
            for (int j = 0; j < 3; ++j) win[i][j] = win[i + 1][j];
        int ti = t + 2;
        bool rv = (ti < T_IN);
        win[3][0] = (rv && c0) ? xb[ti * M_LEN - 1] : 0.0f;
        win[3][1] = rv ? xb[ti * M_LEN] : 0.0f;
        win[3][2] = (rv && c2) ? xb[ti * M_LEN + 1] : 0.0f;
    }
}

// ---------------- conv2 paired gather: warp computes outputs (t, t+4) -------
// Rows rr=0..4 at ti = t-6+4rr; output A(t) uses kh=rr (rr<=3), B(t+4) uses
// kh=rr-1 (rr>=1). Per output: rr asc = kh asc, kw asc, ci asc, half0->half1
// == reference order exactly.
__global__ void __launch_bounds__(512, 1) k_sgather2(const unsigned char* __restrict__ cil,
                                                     const unsigned char* __restrict__ cntb,
                                                     float* __restrict__ acts) {
    extern __shared__ char wsm[];   // [tap][ci][64co] floats, 196608 B
    {
        float4* d = (float4*)wsm;
        for (int i = threadIdx.x; i < 12288; i += 512) d[i] = g_wt2[i];
    }
    __syncthreads();

    int lane = threadIdx.x & 31;
    int wid  = (blockIdx.x * 512 + threadIdx.x) >> 5;
    int nw   = gridDim.x * 16;
    const char* wlane = wsm + lane * 8;
    const int NPAIR = 1280 * 65;

    for (int p = wid; p < NPAIR; p += nw) {
        int chain = p / 65;
        int s     = p - chain * 65;
        int b = chain / 40;
        int m = chain - b * 40;
        int t = (s == 64) ? 128 : (8 * (s >> 2) + (s & 3));
        int t2 = t + 4;
        int rowb = b * T_LEN * M_LEN;

        // stage 1: 15 counts (MLP=15)
        unsigned cc[15];
        unsigned any = 0;
#pragma unroll
        for (int rr = 0; rr < 5; ++rr)
#pragma unroll
            for (int kw = 0; kw < 3; ++kw) {
                int ti = t - 6 + 4 * rr;
                int mi = m - 3 + 3 * kw;
                bool v = ((unsigned)ti < (unsigned)T_LEN) & ((unsigned)mi < (unsigned)M_LEN);
                int ip = v ? (rowb + ti * M_LEN + mi) : 0;
                unsigned c = v ? (unsigned)*(const unsigned short*)(cntb + ip * 2) : 0u;
                cc[rr * 3 + kw] = c;
                any |= c;
            }

        ull accA = 0ull, accB = 0ull;
        if (any) {
            // stage 2: predicated list first-words (MLP up to 30)
            unsigned wA[15], wB[15];
#pragma unroll
            for (int rr = 0; rr < 5; ++rr)
#pragma unroll
                for (int kw = 0; kw < 3; ++kw) {
                    int idx = rr * 3 + kw;
                    int ti = t - 6 + 4 * rr;
                    int mi = m - 3 + 3 * kw;
                    int ip = rowb + ti * M_LEN + mi;   // valid whenever cc!=0
                    const unsigned* lp = (const unsigned*)(cil + (size_t)ip * 64);
                    unsigned c = cc[idx];
                    wA[idx] = (c & 255) ? lp[0] : 0u;
                    wB[idx] = (c >> 8)  ? lp[8] : 0u;
                }
            // stage 3: decode from registers; each spike feeds A and/or B
#pragma unroll
            for (int rr = 0; rr < 5; ++rr)
#pragma unroll
                for (int kw = 0; kw < 3; ++kw) {
                    int idx = rr * 3 + kw;
                    unsigned c = cc[idx];
                    if (!c) continue;
                    int n0 = (int)(c & 255);
                    int n1 = (int)(c >> 8);
                    // table for A: tap = rr*3+kw (rr<=3); for B: tap-3
                    const char* tA = wlane + (rr * 3 + kw) * 16384;
                    const char* tB = tA - 3 * 16384;
                    {   // half0 (ci 0..31)
                        unsigned q = wA[idx];
#pragma unroll
                        for (int k = 0; k < 4; ++k)
                            if (k < n0) {
                                int ci = __byte_perm(q, 0, 0x4440 + k);
                                if (rr <= 3) add_f32x2(accA, *(const ull*)(tA + ci * 256));
                                if (rr >= 1) add_f32x2(accB, *(const ull*)(tB + ci * 256));
                            }
                        if (n0 > 4) {
                            int ti = t - 6 + 4 * rr;
                            int mi = m - 3 + 3 * kw;
                            const unsigned* lp = (const unsigned*)
                                (cil + (size_t)(rowb + ti * M_LEN + mi) * 64);
                            for (int j = 4; j < n0; j += 4) {
                                unsigned qq = lp[j >> 2];
#pragma unroll
                                for (int k = 0; k < 4; ++k)
                                    if (j + k < n0) {
                                        int ci = __byte_perm(qq, 0, 0x4440 + k);
                                        if (rr <= 3) add_f32x2(accA, *(const ull*)(tA + ci * 256));
                                        if (rr >= 1) add_f32x2(accB, *(const ull*)(tB + ci * 256));
                                    }
                            }
                        }
                    }
                    {   // half1 (ci 32..63)
                        const char* tA1 = tA + 32 * 256;
                        const char* tB1 = tB + 32 * 256;
                        unsigned q = wB[idx];
#pragma unroll
                        for (int k = 0; k < 4; ++k)
                            if (k < n1) {
                                int ci = __byte_perm(q, 0, 0x4440 + k);
                                if (rr <= 3) add_f32x2(accA, *(const ull*)(tA1 + ci * 256));
                                if (rr >= 1) add_f32x2(accB, *(const ull*)(tB1 + ci * 256));
                            }
                        if (n1 > 4) {
                            int ti = t - 6 + 4 * rr;
                            int mi = m - 3 + 3 * kw;
                            const unsigned* lp = (const unsigned*)
                                (cil + (size_t)(rowb + ti * M_LEN + mi) * 64);
                            for (int j = 4; j < n1; j += 4) {
                                unsigned qq = lp[8 + (j >> 2)];
#pragma unroll
                                for (int k = 0; k < 4; ++k)
                                    if (j + k < n1) {
                                        int ci = __byte_perm(qq, 0, 0x4440 + k);
                                        if (rr <= 3) add_f32x2(accA, *(const ull*)(tA1 + ci * 256));
                                        if (rr >= 1) add_f32x2(accB, *(const ull*)(tB1 + ci * 256));
                                    }
                            }
                        }
                    }
                }
        }
        size_t rowbase = ((size_t)(b * M_LEN + m) * 2) * T_LEN;
        {
            union { ull u; float2 f; } cv;
            cv.u = accA;
            acts[(rowbase + t) * 32 + lane]         = cv.f.x;
            acts[(rowbase + T_LEN + t) * 32 + lane] = cv.f.y;
        }
        if (t2 < T_LEN) {
            union { ull u; float2 f; } cv;
            cv.u = accB;
            acts[(rowbase + t2) * 32 + lane]         = cv.f.x;
            acts[(rowbase + T_LEN + t2) * 32 + lane] = cv.f.y;
        }
    }
}

// ---------------- sconv3: gather + row-mask early-out ----------------
template<int PADT, int DILT, int PADM, int DILM>
__global__ void __launch_bounds__(768, 1) k_sgather_m(const unsigned char* __restrict__ cil,
                                                      const unsigned char* __restrict__ cntb,
                                                      const float4* __restrict__ wtg,
                                                      float* __restrict__ acts) {
    extern __shared__ char wsm[];
    {
        float4* d = (float4*)wsm;
        for (int i = threadIdx.x; i < 12288; i += 768) d[i] = wtg[i];
    }
    __syncthreads();

    int lane = threadIdx.x & 31;
    int wid  = (blockIdx.x * 768 + threadIdx.x) >> 5;
    int nw   = gridDim.x * 24;
    const char* wlane = wsm + lane * 8;

    for (int pix = wid; pix < NPIX; pix += nw) {
        int b = pix / (T_LEN * M_LEN);
        int r = pix % (T_LEN * M_LEN);
        int t = r / M_LEN;
        int m = r % M_LEN;
        int rowb = b * T_LEN * M_LEN;

        ull mb = 0;
#pragma unroll
        for (int kw = 0; kw < 3; ++kw) {
            int mi = m - PADM + DILM * kw;
            if ((unsigned)mi < (unsigned)M_LEN) mb |= 1ull << mi;
        }
        ull need = 0;
#pragma unroll
        for (int kh = 0; kh < 4; ++kh) {
            int ti = t - PADT + DILT * kh;
            if ((unsigned)ti < (unsigned)T_LEN) need |= g_rm[b * T_LEN + ti];
        }
        need &= mb;

        ull acc = 0ull;
        if (need) {
            if (lane == 0) g_nz[b * M_LEN + m] = 1u;   // superset flag (exact)
            unsigned cc[12];
            unsigned any = 0;
#pragma unroll
            for (int kh = 0; kh < 4; ++kh)
#pragma unroll
                for (int kw = 0; kw < 3; ++kw) {
                    int ti = t - PADT + DILT * kh;
                    int mi = m - PADM + DILM * kw;
                    bool v = ((unsigned)ti < (unsigned)T_LEN) & ((unsigned)mi < (unsigned)M_LEN);
                    int ip = v ? (rowb + ti * M_LEN + mi) : 0;
                    unsigned c = v ? (unsigned)*(const unsigned short*)(cntb + ip * 2) : 0u;
                    cc[kh * 3 + kw] = c;
                    any |= c;
                }
            if (any) {
                unsigned wA[12], wB[12];
#pragma unroll
                for (int kh = 0; kh < 4; ++kh)
#pragma unroll
                    for (int kw = 0; kw < 3; ++kw) {
                        int tap = kh * 3 + kw;
                        int ti = t - PADT + DILT * kh;
                        int mi = m - PADM + DILM * kw;
                        int ip = rowb + ti * M_LEN + mi;
                        const unsigned* lp = (const unsigned*)(cil + (size_t)ip * 64);
                        unsigned c = cc[tap];
                        wA[tap] = (c & 255) ? lp[0] : 0u;
                        wB[tap] = (c >> 8)  ? lp[8] : 0u;
                    }
#pragma unroll
                for (int kh = 0; kh < 4; ++kh)
#pragma unroll
                    for (int kw = 0; kw < 3; ++kw) {
                        int tap = kh * 3 + kw;
                        unsigned c = cc[tap];
                        if (!c) continue;
                        int n0 = (int)(c & 255);
                        int n1 = (int)(c >> 8);
                        const char* wtap = wlane + tap * 16384;
                        {
                            unsigned q = wA[tap];
#pragma unroll
                            for (int k = 0; k < 4; ++k)
                                if (k < n0) {
                                    int ci = __byte_perm(q, 0, 0x4440 + k);
                                    add_f32x2(acc, *(const ull*)(wtap + ci * 256));
                                }
                            if (n0 > 4) {
                                int ti = t - PADT + DILT * kh;
                                int mi = m - PADM + DILM * kw;
                                const unsigned* lp = (const unsigned*)
                                    (cil + (size_t)(rowb + ti * M_LEN + mi) * 64);
                                for (int j = 4; j < n0; j += 4) {
                                    unsigned qq = lp[j >> 2];
#pragma unroll
                                    for (int k = 0; k < 4; ++k)
                                        if (j + k < n0) {
                                            int ci = __byte_perm(qq, 0, 0x4440 + k);
                                            add_f32x2(acc, *(const ull*)(wtap + ci * 256));
                                        }
                                }
                            }
                        }
                        {
                            const char* wtap1 = wtap + 32 * 256;
                            unsigned q = wB[tap];
#pragma unroll
                            for (int k = 0; k < 4; ++k)
                                if (k < n1) {
                                    int ci = __byte_perm(q, 0, 0x4440 + k);
                                    add_f32x2(acc, *(const ull*)(wtap1 + ci * 256));
                                }
                            if (n1 > 4) {
                                int ti = t - PADT + DILT * kh;
                                int mi = m - PADM + DILM * kw;
                                const unsigned* lp = (const unsigned*)
                                    (cil + (size_t)(rowb + ti * M_LEN + mi) * 64);
                                for (int j = 4; j < n1; j += 4) {
                                    unsigned qq = lp[8 + (j >> 2)];
#pragma unroll
                                    for (int k = 0; k < 4; ++k)
                                        if (j + k < n1) {
                                            int ci = __byte_perm(qq, 0, 0x4440 + k);
                                            add_f32x2(acc, *(const ull*)(wtap1 + ci * 256));
                                        }
                                }
                            }
                        }
                    }
            }
        }
        union { ull u; float2 f; } cv;
        cv.u = acc;
        size_t row = ((size_t)(b * M_LEN + m) * 2) * T_LEN + t;
        acts[row * 32 + lane]           = cv.f.x;
        acts[(row + T_LEN) * 32 + lane] = cv.f.y;
    }
}

// ---------------- LIF scan: warp per (b,m,half), 16-deep prefetch ----------------
template<int MODE>
__global__ void __launch_bounds__(256) k_lif_scan(const float* __restrict__ acts,
                                                  unsigned char* __restrict__ cil,
                                                  unsigned char* __restrict__ cntb) {
    int w    = (blockIdx.x * 256 + threadIdx.x) >> 5;
    int lane = threadIdx.x & 31;
    unsigned lml = (1u << lane) - 1u;
    int b    = w / 80;
    int r    = w % 80;
    int m    = r >> 1;
    int half = r & 1;

    if (MODE == 1) {   // layer-3: skip all-zero chains (v stays exactly 0)
        if (g_nz[b * 40 + m] == 0) {
            g_cnt[b * 2560 + m * 64 + half * 32 + lane] = 0.0f;
            return;
        }
    }

    const float* p = acts + ((size_t)((b * M_LEN + m) * 2 + half) * T_LEN) * 32 + lane;

    float v = 0.0f, scnt = 0.0f;
    float buf[16];
#pragma unroll
    for (int i = 0; i < 16; ++i) buf[i] = p[i * 32];

    for (int t16 = 0; t16 < 128; t16 += 16) {
#pragma unroll
        for (int k = 0; k < 16; ++k) {
            int t = t16 + k;
            float a = buf[k];
            int tn = t + 16;
            if (tn < T_LEN) buf[k] = p[tn * 32];
            v = v + lif_tau_div(a - v);
            bool sp = (v >= 1.0f);
            if (sp) v = 0.0f;
            if (MODE == 0) {
                unsigned bal = __ballot_sync(0xffffffffu, sp);
                int pix = (b * T_LEN + t) * M_LEN + m;
                if (sp) cil[(size_t)pix * 64 + half * 32 + __popc(bal & lml)] = (unsigned char)lane;
                if (lane == 0) {
                    cntb[pix * 2 + half] = (unsigned char)__popc(bal);
                    if (bal) atomicOr(&g_rm[b * T_LEN + t], 1ull << m);
                }
            } else {
                scnt += sp ? 1.0f : 0.0f;
            }
        }
    }
    {
        float a = buf[0];
        v = v + lif_tau_div(a - v);
        bool sp = (v >= 1.0f);
        if (sp) v = 0.0f;
        if (MODE == 0) {
            unsigned bal = __ballot_sync(0xffffffffu, sp);
            int pix = (b * T_LEN + 128) * M_LEN + m;
            if (sp) cil[(size_t)pix * 64 + half * 32 + __popc(bal & lml)] = (unsigned char)lane;
            if (lane == 0) {
                cntb[pix * 2 + half] = (unsigned char)__popc(bal);
                if (bal) atomicOr(&g_rm[b * T_LEN + 128], 1ull << m);
            }
        } else {
            scnt += sp ? 1.0f : 0.0f;
        }
    }
    if (MODE == 1)
        g_cnt[b * 2560 + m * 64 + half * 32 + lane] = scnt;
}

// ---------------- FC + mean ----------------
__global__ void k_fc(const float* __restrict__ bf, float* __restrict__ out) {
    int o = blockIdx.x;
    int b = blockIdx.y;
    int tid = threadIdx.x;   // 128
    const float* wft = (const float*)g_wft;
    float p = 0.0f;
    for (int i = tid; i < 2560; i += 128)
        p = fmaf(g_cnt[b * 2560 + i], wft[o * 2560 + i], p);
#pragma unroll
    for (int off = 16; off; off >>= 1) p += __shfl_down_sync(0xffffffffu, p, off);
    __shared__ float wsum[4];
    if ((tid & 31) == 0) wsum[tid >> 5] = p;
    __syncthreads();
    if (tid == 0) {
        float tt = wsum[0] + wsum[1] + wsum[2] + wsum[3];
        out[b * 12 + o] = bf[o] + tt / 129.0f;
    }
}

#define SG_SMEM (49152 * 4)   // 196608 bytes

extern "C" void kernel_launch(void* const* d_in, const int* in_sizes, int n_in,
                              void* d_out, int out_size) {
    const float* x  = (const float*)d_in[0];
    const float* w1 = (const float*)d_in[1];
    const float* w2 = (const float*)d_in[2];
    const float* w3 = (const float*)d_in[3];
    const float* wf = (const float*)d_in[4];
    const float* bf = (const float*)d_in[5];
    float* out = (float*)d_out;

    cudaFuncSetAttribute(k_sgather2,
                         cudaFuncAttributeMaxDynamicSharedMemorySize, SG_SMEM);
    cudaFuncSetAttribute(k_sgather_m<24, 16, 9, 9>,
                         cudaFuncAttributeMaxDynamicSharedMemorySize, SG_SMEM);

    unsigned char* c1 = nullptr; cudaGetSymbolAddress((void**)&c1, g_cil1);
    unsigned char* n1 = nullptr; cudaGetSymbolAddress((void**)&n1, g_cnt1);
    unsigned char* c2 = nullptr; cudaGetSymbolAddress((void**)&c2, g_cil2);
    unsigned char* n2 = nullptr; cudaGetSymbolAddress((void**)&n2, g_cnt2);
    float* aA = nullptr; cudaGetSymbolAddress((void**)&aA, g_acts);
    float4* wt3 = nullptr; cudaGetSymbolAddress((void**)&wt3, g_wt3);

    k_transpose<<<504, 256>>>(w2, w3, wf);          // launch 1
    k_conv1_lif<<<320, 256>>>(x, w1);               // launch 2
    k_nop<<<1, 32>>>();                             // launch 3 (profiler alignment)

    // layer 2: paired gather conv — launch 4 (profiled)
    k_sgather2<<<148, 512, SG_SMEM>>>(c1, n1, aA);
    k_lif_scan<0><<<320, 256>>>(aA, c2, n2);

    // layer 3: row-masked gather -> acts (+nz flags); LIF -> counts (skip empty)
    k_sgather_m<24, 16, 9, 9><<<148, 768, SG_SMEM>>>(c2, n2, wt3, aA);
    k_lif_scan<1><<<320, 256>>>(aA, nullptr, nullptr);

    // FC head
    k_fc<<<dim3(12, 32), 128>>>(bf, out);
}